// round 10
// baseline (speedup 1.0000x reference)
#include <cuda_runtime.h>
#include <cstdint>

// Problem constants
#define NXC 64
#define NYC 64
#define SCALE 16
#define PP 15
#define BB 4
#define CC 3
#define HH 1024
#define WW 1024
#define HW (HH*WW)
#define NNODES 4096
#define CHW (CC*HH*WW)
#define NPAIRS_HALF (BB * 63 * 64)      // 16128
#define NPAIRS (2 * NPAIRS_HALF)        // 32256
static const long long A_ELEMS = (long long)BB * NNODES * NNODES;  // 67108864

#define TOTAL_BLOCKS 1184                // 148 SMs x 8 blocks = one wave
#define THREADS 256
#define CHUNK_F4 1024                    // 1024 float4 = 16KB = one A row

// Work item layout:
//  per plane p = b*3+c (12 planes), 320 items: [256 copy chunks][64 edge strips]
//  then 16384 A-row items.
#define PLANE_ITEMS 320
#define COPY_EDGE_ITEMS (12 * PLANE_ITEMS)           // 3840
#define NA_ROWS 16384
#define NITEMS (COPY_EDGE_ITEMS + NA_ROWS)           // 20224
#define NEDGE_ITEMS 768

// Per-channel edge scratch: [c][pair]; pair: [0,16128) dv, [16128,32256) dh
__device__ float    g_scratch[CC * NPAIRS];
__device__ unsigned g_chunk = 0;         // work-stealing counter
__device__ unsigned g_edges_done = 0;    // completed edge items
__device__ unsigned g_done = 0;          // block completion counter

__global__ void __launch_bounds__(THREADS, 8)
fused_kernel(const float* __restrict__ data,
             float4* __restrict__ out,
             long long a4, long long total4) {
    const float4* src = (const float4*)data;
    const float4 z = make_float4(0.f, 0.f, 0.f, 0.f);
    int tid = threadIdx.x;

    __shared__ unsigned s_next;
    __shared__ int s_ok;                 // edges known complete (block-local cache)
    if (tid == 0) { s_ok = 0; s_next = atomicAdd(&g_chunk, 1u); }
    __syncthreads();
    unsigned w = s_next;

    while (w < NITEMS) {
        if (tid == 0) s_next = atomicAdd(&g_chunk, 1u);   // prefetch next item

        if (w < COPY_EDGE_ITEMS) {
            unsigned plane = w / PLANE_ITEMS;             // b*3 + c
            unsigned r = w - plane * PLANE_ITEMS;
            if (r < 256) {
                // -------- copy chunk: 4 rows of this plane --------
                long long sidx = (long long)plane * (HW / 4) + (long long)r * CHUNK_F4 + tid;
                long long oidx = a4 + sidx;
                #pragma unroll
                for (int k = 0; k < CHUNK_F4 / THREADS; k++) {
                    long long i = oidx + (long long)k * THREADS;
                    if (i < total4) __stcs(&out[i], src[sidx + (long long)k * THREADS]);
                }
                __syncthreads();
            } else {
                // -------- edge strip item (one plane, one y) --------
                int b = plane / 3, c = plane - b * 3;
                int y = r - 256;
                int x = tid >> 2;
                int q = tid & 3;                          // q==3 masks col 15
                bool has_v = (y < 63);
                bool has_h = (x < 63);
                const float4* cb = (const float4*)data + (long long)plane * (HW / 4)
                                 + (long long)(y * SCALE) * (WW / 4);
                float sv = 0.f, sh = 0.f;
                #pragma unroll 5
                for (int i = 0; i < PP; i++) {
                    const float4* rp = cb + i * (WW / 4);
                    float4 a = __ldg(rp + tid);
                    if (has_v) {
                        float4 v = __ldg(rp + 4096 + tid);     // +16 rows
                        sv += fabsf(a.x - v.x) + fabsf(a.y - v.y) + fabsf(a.z - v.z);
                        if (q < 3) sv += fabsf(a.w - v.w);
                    }
                    if (has_h) {
                        float4 hh = __ldg(rp + tid + 4);       // +16 cols
                        sh += fabsf(a.x - hh.x) + fabsf(a.y - hh.y) + fabsf(a.z - hh.z);
                        if (q < 3) sh += fabsf(a.w - hh.w);
                    }
                }
                sv += __shfl_xor_sync(0xffffffffu, sv, 1);
                sv += __shfl_xor_sync(0xffffffffu, sv, 2);
                sh += __shfl_xor_sync(0xffffffffu, sh, 1);
                sh += __shfl_xor_sync(0xffffffffu, sh, 2);
                float* scr = g_scratch + c * NPAIRS;
                if (q == 0) {
                    if (has_v) scr[b * 4032 + y * 64 + x] = sv;
                    if (has_h) scr[NPAIRS_HALF + b * 4032 + y * 63 + x] = sh;
                }
                __syncthreads();                 // all strip stores issued (CTA)
                if (tid == 0) {
                    __threadfence();             // publish before counting
                    atomicAdd(&g_edges_done, 1u);
                }
                __syncthreads();
            }
        } else {
            // -------- A row: zeros + direct patch of <=4 edge values --------
            unsigned r = w - COPY_EDGE_ITEMS;              // global A row
            int b = r >> 12;
            int n = r & 4095;
            float4* row4 = out + (long long)r * CHUNK_F4;
            #pragma unroll
            for (int k = 0; k < CHUNK_F4 / THREADS; k++)
                __stcs(&row4[tid + k * THREADS], z);

            if (tid == 0 && !s_ok) {
                while (*(volatile unsigned*)&g_edges_done < NEDGE_ITEMS) { }
                __threadfence();                 // acquire edge scratch
                s_ok = 1;
            }
            __syncthreads();                     // zeros done + scratch visible

            int y = n >> 6, x = n & 63;
            float* rowf = (float*)row4;
            if (tid == 0 && y > 0) {             // up: dv[y-1, x]
                int p = b * 4032 + (y - 1) * 64 + x;
                rowf[n - 64] = g_scratch[p] + g_scratch[NPAIRS + p] + g_scratch[2 * NPAIRS + p];
            }
            if (tid == 1 && y < 63) {            // down: dv[y, x]
                int p = b * 4032 + y * 64 + x;
                rowf[n + 64] = g_scratch[p] + g_scratch[NPAIRS + p] + g_scratch[2 * NPAIRS + p];
            }
            if (tid == 2 && x > 0) {             // left: dh[y, x-1]
                int p = NPAIRS_HALF + b * 4032 + y * 63 + (x - 1);
                rowf[n - 1] = g_scratch[p] + g_scratch[NPAIRS + p] + g_scratch[2 * NPAIRS + p];
            }
            if (tid == 3 && x < 63) {            // right: dh[y, x]
                int p = NPAIRS_HALF + b * 4032 + y * 63 + x;
                rowf[n + 1] = g_scratch[p] + g_scratch[NPAIRS + p] + g_scratch[2 * NPAIRS + p];
            }
            __syncthreads();
        }
        w = s_next;
    }

    // -------- epilogue: last block resets counters for next graph replay --------
    __syncthreads();
    if (tid == 0) {
        unsigned d = atomicAdd(&g_done, 1u);
        if (d == TOTAL_BLOCKS - 1) {
            g_chunk = 0;
            g_edges_done = 0;
            g_done = 0;
        }
    }
}

extern "C" void kernel_launch(void* const* d_in, const int* in_sizes, int n_in,
                              void* d_out, int out_size) {
    const float* data = (const float*)d_in[0];
    float* out = (float*)d_out;

    long long a_elems = A_ELEMS;
    long long total = (long long)out_size;
    if (total < a_elems) a_elems = total;
    long long a4 = a_elems >> 2;
    long long total4 = total >> 2;

    fused_kernel<<<TOTAL_BLOCKS, THREADS>>>(data, (float4*)out, a4, total4);
}

// round 12
// speedup vs baseline: 1.0013x; 1.0013x over previous
#include <cuda_runtime.h>
#include <cstdint>

// Problem constants
#define NXC 64
#define NYC 64
#define SCALE 16
#define PP 15
#define BB 4
#define CC 3
#define HH 1024
#define WW 1024
#define HW (HH*WW)
#define NNODES 4096
#define CHW (CC*HH*WW)
#define NPAIRS_HALF (BB * 63 * 64)      // 16128
#define NPAIRS (2 * NPAIRS_HALF)        // 32256
static const long long A_ELEMS = (long long)BB * NNODES * NNODES;  // 67108864

#define EDGE_BLOCKS 256                  // static: one per (b, y) strip, at t=0
#define TOTAL_BLOCKS 1184                // 148 SMs x 8 blocks = one wave
#define THREADS 256
#define CHUNK_F4 1024                    // 16KB item = one A row / 4 image rows

// Steal queue: [0, 3072) copy chunks, [3072, 19456) A rows.
#define COPY_ITEMS 3072
#define NA_ROWS 16384
#define NITEMS (COPY_ITEMS + NA_ROWS)    // 19456

// Edge scratch (summed over channels): [0,16128) dv, [16128,32256) dh
__device__ float    g_scratch[NPAIRS];
__device__ unsigned g_chunk = 0;         // work-stealing counter
__device__ unsigned g_edges_done = 0;    // completed edge blocks (0..256)
__device__ unsigned g_done = 0;          // block completion counter

__global__ void __launch_bounds__(THREADS, 8)
fused_kernel(const float* __restrict__ data,
             float4* __restrict__ out,
             long long a4) {
    const float4* src = (const float4*)data;
    const float4 z = make_float4(0.f, 0.f, 0.f, 0.f);
    int tid = threadIdx.x;

    // ===================== static edge phase (blocks 0..255) =====================
    if (blockIdx.x < EDGE_BLOCKS) {
        int e = blockIdx.x;
        int b = e >> 6;
        int y = e & 63;
        int x = tid >> 2;            // cell column bin
        int q = tid & 3;             // quarter (q==3 masks col 15)
        bool has_v = (y < 63);
        bool has_h = (x < 63);

        const float4* base0 = (const float4*)(data + (long long)b * CHW
                                                    + (long long)(y * SCALE) * WW);
        float sv = 0.f, sh = 0.f;
        #pragma unroll
        for (int c = 0; c < CC; c++) {
            const float4* cb = base0 + (long long)c * (HW / 4);
            #pragma unroll 5
            for (int i = 0; i < PP; i++) {
                const float4* rp = cb + i * (WW / 4);
                float4 a = __ldg(rp + tid);
                if (has_v) {
                    float4 v = __ldg(rp + 4096 + tid);     // +16 rows
                    sv += fabsf(a.x - v.x) + fabsf(a.y - v.y) + fabsf(a.z - v.z);
                    if (q < 3) sv += fabsf(a.w - v.w);
                }
                if (has_h) {
                    float4 hh = __ldg(rp + tid + 4);       // +16 cols
                    sh += fabsf(a.x - hh.x) + fabsf(a.y - hh.y) + fabsf(a.z - hh.z);
                    if (q < 3) sh += fabsf(a.w - hh.w);
                }
            }
        }
        sv += __shfl_xor_sync(0xffffffffu, sv, 1);
        sv += __shfl_xor_sync(0xffffffffu, sv, 2);
        sh += __shfl_xor_sync(0xffffffffu, sh, 1);
        sh += __shfl_xor_sync(0xffffffffu, sh, 2);
        if (q == 0) {
            if (has_v) g_scratch[b * 4032 + y * 64 + x] = sv;
            if (has_h) g_scratch[NPAIRS_HALF + b * 4032 + y * 63 + x] = sh;
        }
        __syncthreads();
        if (tid == 0) {
            __threadfence();                 // publish scratch before counting
            atomicAdd(&g_edges_done, 1u);
        }
    }

    // ===================== work-stealing fill / copy / patch =====================
    __shared__ unsigned s_next;
    bool edges_ok = false;                   // per-thread readiness flag (tids 0..3 use it)

    if (tid == 0) s_next = atomicAdd(&g_chunk, 1u);
    __syncthreads();
    unsigned w = s_next;

    while (w < NITEMS) {
        if (tid == 0) s_next = atomicAdd(&g_chunk, 1u);   // prefetch next item

        if (w < COPY_ITEMS) {
            // -------- copy chunk (16KB, exact fit, no bounds checks) --------
            long long sidx = (long long)w * CHUNK_F4 + tid;
            #pragma unroll
            for (int k = 0; k < CHUNK_F4 / THREADS; k++)
                __stcs(&out[a4 + sidx + k * THREADS], src[sidx + k * THREADS]);
            __syncthreads();
        } else {
            // -------- A row: zeros, then patch <=4 edge entries --------
            unsigned r = w - COPY_ITEMS;                   // global A row 0..16383
            float4* row4 = out + (long long)r * CHUNK_F4;
            #pragma unroll
            for (int k = 0; k < CHUNK_F4 / THREADS; k++)
                __stcs(&row4[tid + k * THREADS], z);
            __syncthreads();                               // zeros ordered before patch

            if (tid < 4) {
                if (!edges_ok) {                           // one-time check; edges finish ~10us,
                    while (*(volatile unsigned*)&g_edges_done < EDGE_BLOCKS) { }
                    __threadfence();                       // acquire scratch
                    edges_ok = true;
                }
                int b = r >> 12;
                int n = r & 4095;
                int y = n >> 6, x = n & 63;
                float* rowf = (float*)row4;
                if (tid == 0 && y > 0)   rowf[n - 64] = g_scratch[b * 4032 + (y - 1) * 64 + x];
                if (tid == 1 && y < 63)  rowf[n + 64] = g_scratch[b * 4032 + y * 64 + x];
                if (tid == 2 && x > 0)   rowf[n - 1]  = g_scratch[NPAIRS_HALF + b * 4032 + y * 63 + x - 1];
                if (tid == 3 && x < 63)  rowf[n + 1]  = g_scratch[NPAIRS_HALF + b * 4032 + y * 63 + x];
            }
            __syncthreads();                               // protect s_next
        }
        w = s_next;
    }

    // ===================== epilogue: reset counters for next replay =====================
    __syncthreads();
    if (tid == 0) {
        unsigned d = atomicAdd(&g_done, 1u);
        if (d == TOTAL_BLOCKS - 1) {         // all blocks finished all work
            g_chunk = 0;
            g_edges_done = 0;
            g_done = 0;
        }
    }
}

extern "C" void kernel_launch(void* const* d_in, const int* in_sizes, int n_in,
                              void* d_out, int out_size) {
    const float* data = (const float*)d_in[0];
    float* out = (float*)d_out;

    long long a_elems = A_ELEMS;
    long long total = (long long)out_size;
    if (total < a_elems) a_elems = total;
    long long a4 = a_elems >> 2;

    fused_kernel<<<TOTAL_BLOCKS, THREADS>>>(data, (float4*)out, a4);
}